// round 3
// baseline (speedup 1.0000x reference)
#include <cuda_runtime.h>
#include <math.h>
#include <stdint.h>

// Multiresolution hash-grid encoding (Instant-NGP style).
// One thread per (point, level). Level is the fast index so the float2
// output store is perfectly coalesced (out row = 16 contiguous float2).

#define N_LEVELS 16
#define LOG2_T   19
#define T_MASK   ((1u << LOG2_T) - 1u)

struct ResParams { float r[N_LEVELS]; };

__global__ __launch_bounds__(256) void hashgrid_kernel(
    const float* __restrict__ x,        // [N,3]
    const float2* __restrict__ table,   // [T, 2] as float2
    float2* __restrict__ out,           // [N, 16] float2 rows
    ResParams rp, int N)
{
    int gid = blockIdx.x * 256 + threadIdx.x;
    int n = gid >> 4;
    if (n >= N) return;
    int l = gid & 15;

    // position (lanes sharing a point broadcast from L1)
    const float px = __ldg(&x[n * 3 + 0]);
    const float py = __ldg(&x[n * 3 + 1]);
    const float pz = __ldg(&x[n * 3 + 2]);

    const float res = rp.r[l];
    const float sx = px * res;
    const float sy = py * res;
    const float sz = pz * res;

    const float fx = floorf(sx);
    const float fy = floorf(sy);
    const float fz = floorf(sz);

    const int ix0 = (int)fx, iy0 = (int)fy, iz0 = (int)fz;
    const int ix1 = ix0 + 1, iy1 = iy0 + 1, iz1 = iz0 + 1;
    // (ceil differs from floor+1 only when the frac weight is exactly 0,
    //  in which case that corner's contribution is exactly 0 anyway)

    const float dx = sx - fx;
    const float dy = sy - fy;
    const float dz = sz - fz;

    // hash terms: h = (cx*1) ^ (cy*P1) ^ (cz*P2), int32 wraparound == unsigned mul
    const unsigned hx0 = (unsigned)ix0;
    const unsigned hx1 = (unsigned)ix1;
    const unsigned hy0 = (unsigned)iy0 * 2654435761u;
    const unsigned hy1 = (unsigned)iy1 * 2654435761u;
    const unsigned hz0 = (unsigned)iz0 * 805459861u;
    const unsigned hz1 = (unsigned)iz1 * 805459861u;

    const unsigned h000 = (hx0 ^ hy0 ^ hz0) & T_MASK;
    const unsigned h100 = (hx1 ^ hy0 ^ hz0) & T_MASK;
    const unsigned h010 = (hx0 ^ hy1 ^ hz0) & T_MASK;
    const unsigned h001 = (hx0 ^ hy0 ^ hz1) & T_MASK;
    const unsigned h110 = (hx1 ^ hy1 ^ hz0) & T_MASK;
    const unsigned h101 = (hx1 ^ hy0 ^ hz1) & T_MASK;
    const unsigned h011 = (hx0 ^ hy1 ^ hz1) & T_MASK;
    const unsigned h111 = (hx1 ^ hy1 ^ hz1) & T_MASK;

    // 8 independent gathers (MLP=8), all L2-resident (table = 4 MB)
    const float2 v000 = __ldg(&table[h000]);
    const float2 v100 = __ldg(&table[h100]);
    const float2 v010 = __ldg(&table[h010]);
    const float2 v001 = __ldg(&table[h001]);
    const float2 v110 = __ldg(&table[h110]);
    const float2 v101 = __ldg(&table[h101]);
    const float2 v011 = __ldg(&table[h011]);
    const float2 v111 = __ldg(&table[h111]);

    const float wx0 = 1.0f - dx, wx1 = dx;
    const float wy0 = 1.0f - dy, wy1 = dy;
    const float wz0 = 1.0f - dz, wz1 = dz;

    // trilinear interpolation (factored form of sum_c v_c * wx*wy*wz)
    float a00x = v000.x * wx0 + v100.x * wx1;
    float a00y = v000.y * wx0 + v100.y * wx1;
    float a10x = v010.x * wx0 + v110.x * wx1;
    float a10y = v010.y * wx0 + v110.y * wx1;
    float a01x = v001.x * wx0 + v101.x * wx1;
    float a01y = v001.y * wx0 + v101.y * wx1;
    float a11x = v011.x * wx0 + v111.x * wx1;
    float a11y = v011.y * wx0 + v111.y * wx1;

    float b0x = a00x * wy0 + a10x * wy1;
    float b0y = a00y * wy0 + a10y * wy1;
    float b1x = a01x * wy0 + a11x * wy1;
    float b1y = a01y * wy0 + a11y * wy1;

    float2 r;
    r.x = b0x * wz0 + b1x * wz1;
    r.y = b0y * wz0 + b1y * wz1;

    out[gid] = r;   // coalesced: row n = 16 consecutive float2
}

extern "C" void kernel_launch(void* const* d_in, const int* in_sizes, int n_in,
                              void* d_out, int out_size)
{
    const float*  x     = (const float*)d_in[0];
    const float2* table = (const float2*)d_in[1];
    float2*       out   = (float2*)d_out;

    const int N = in_sizes[0] / 3;

    // Resolutions: replicate numpy double-precision computation bit-for-bit
    // (same glibc pow on the same host as the reference).
    ResParams rp;
    {
        const double growth = exp((log(128.0) - log(16.0)) / (double)(N_LEVELS - 1));
        for (int l = 0; l < N_LEVELS; ++l) {
            rp.r[l] = (float)floor(16.0 * pow(growth, (double)l));
        }
    }

    const long long total = (long long)N * N_LEVELS;
    const int threads = 256;
    const int blocks = (int)((total + threads - 1) / threads);
    hashgrid_kernel<<<blocks, threads>>>(x, table, out, rp, N);
}

// round 4
// speedup vs baseline: 1.0192x; 1.0192x over previous
#include <cuda_runtime.h>
#include <math.h>
#include <stdint.h>

// Multiresolution hash-grid encoding (Instant-NGP style).
// One thread per (point, level), level fast -> coalesced float2 output.
//
// Gather-merging trick: hash = x ^ (y*P1) ^ (z*P2) with prime 1 on x.
// For the corner pair (x0, x0+1): if x0 is even, x0+1 == x0^1, so the two
// hashed indices are h and h^1 -> one 16B-aligned float4 covers both corners.
// We always load the float4 (it always contains the x0 corner), and only
// issue a second 8B gather when x0 is odd. Cuts L1 gather wavefronts ~25%.

#define N_LEVELS 16
#define LOG2_T   19
#define T_MASK   ((1u << LOG2_T) - 1u)

struct ResParams { float r[N_LEVELS]; };

__global__ __launch_bounds__(256) void hashgrid_kernel(
    const float* __restrict__ x,        // [N,3]
    const float2* __restrict__ table,   // [T] float2
    float2* __restrict__ out,           // [N,16] float2
    ResParams rp, int N)
{
    int gid = blockIdx.x * 256 + threadIdx.x;
    int n = gid >> 4;
    if (n >= N) return;
    int l = gid & 15;

    const float px = __ldg(&x[n * 3 + 0]);
    const float py = __ldg(&x[n * 3 + 1]);
    const float pz = __ldg(&x[n * 3 + 2]);

    const float res = rp.r[l];
    const float sx = px * res;
    const float sy = py * res;
    const float sz = pz * res;

    const float fx = floorf(sx);
    const float fy = floorf(sy);
    const float fz = floorf(sz);

    const int ix0 = (int)fx, iy0 = (int)fy, iz0 = (int)fz;

    const float dx = sx - fx;
    const float dy = sy - fy;
    const float dz = sz - fz;

    // hash terms (int32 overflow == unsigned wraparound)
    const unsigned x0u = (unsigned)ix0;
    const unsigned hy0 = (unsigned)iy0 * 2654435761u;
    const unsigned hy1 = (unsigned)(iy0 + 1) * 2654435761u;
    const unsigned hz0 = (unsigned)iz0 * 805459861u;
    const unsigned hz1 = (unsigned)(iz0 + 1) * 805459861u;

    // 4 (y,z) corner groups; within each, the x-pair shares the "rest" term.
    const unsigned g00 = hy0 ^ hz0;
    const unsigned g10 = hy1 ^ hz0;
    const unsigned g01 = hy0 ^ hz1;
    const unsigned g11 = hy1 ^ hz1;

    const unsigned h000 = (x0u ^ g00) & T_MASK;
    const unsigned h010 = (x0u ^ g10) & T_MASK;
    const unsigned h001 = (x0u ^ g01) & T_MASK;
    const unsigned h011 = (x0u ^ g11) & T_MASK;

    const unsigned x1u  = x0u + 1u;
    const unsigned h100 = (x1u ^ g00) & T_MASK;
    const unsigned h110 = (x1u ^ g10) & T_MASK;
    const unsigned h101 = (x1u ^ g01) & T_MASK;
    const unsigned h111 = (x1u ^ g11) & T_MASK;

    const bool xeven = (x0u & 1u) == 0u;   // then h1xx == h0xx ^ 1

    // Always: 4 independent float4 loads (each covers the x0 corner, and
    // also the x1 corner when x0 is even). 16B-aligned, 1 sector each.
    const float4 q00 = __ldg((const float4*)&table[h000 & ~1u]);
    const float4 q10 = __ldg((const float4*)&table[h010 & ~1u]);
    const float4 q01 = __ldg((const float4*)&table[h001 & ~1u]);
    const float4 q11 = __ldg((const float4*)&table[h011 & ~1u]);

    // Odd-x0 only: separate gathers for the x1 corners (predicated).
    float2 e00, e10, e01, e11;
    if (!xeven) {
        e00 = __ldg(&table[h100]);
        e10 = __ldg(&table[h110]);
        e01 = __ldg(&table[h101]);
        e11 = __ldg(&table[h111]);
    }

    // Split each float4 into (entry at even index, entry at odd index),
    // then pick which half is the x0 corner by h's parity.
    const float2 q00lo = make_float2(q00.x, q00.y), q00hi = make_float2(q00.z, q00.w);
    const float2 q10lo = make_float2(q10.x, q10.y), q10hi = make_float2(q10.z, q10.w);
    const float2 q01lo = make_float2(q01.x, q01.y), q01hi = make_float2(q01.z, q01.w);
    const float2 q11lo = make_float2(q11.x, q11.y), q11hi = make_float2(q11.z, q11.w);

    const bool p00 = (h000 & 1u), p10 = (h010 & 1u), p01 = (h001 & 1u), p11 = (h011 & 1u);

    const float2 v000 = p00 ? q00hi : q00lo;
    const float2 v010 = p10 ? q10hi : q10lo;
    const float2 v001 = p01 ? q01hi : q01lo;
    const float2 v011 = p11 ? q11hi : q11lo;

    // x1 corner: other half of the float4 when x0 even, else the extra gather.
    const float2 v100 = xeven ? (p00 ? q00lo : q00hi) : e00;
    const float2 v110 = xeven ? (p10 ? q10lo : q10hi) : e10;
    const float2 v101 = xeven ? (p01 ? q01lo : q01hi) : e01;
    const float2 v111 = xeven ? (p11 ? q11lo : q11hi) : e11;

    const float wx0 = 1.0f - dx, wx1 = dx;
    const float wy0 = 1.0f - dy, wy1 = dy;
    const float wz0 = 1.0f - dz, wz1 = dz;

    // trilinear interpolation (factored)
    float a00x = v000.x * wx0 + v100.x * wx1;
    float a00y = v000.y * wx0 + v100.y * wx1;
    float a10x = v010.x * wx0 + v110.x * wx1;
    float a10y = v010.y * wx0 + v110.y * wx1;
    float a01x = v001.x * wx0 + v101.x * wx1;
    float a01y = v001.y * wx0 + v101.y * wx1;
    float a11x = v011.x * wx0 + v111.x * wx1;
    float a11y = v011.y * wx0 + v111.y * wx1;

    float b0x = a00x * wy0 + a10x * wy1;
    float b0y = a00y * wy0 + a10y * wy1;
    float b1x = a01x * wy0 + a11x * wy1;
    float b1y = a01y * wy0 + a11y * wy1;

    float2 r;
    r.x = b0x * wz0 + b1x * wz1;
    r.y = b0y * wz0 + b1y * wz1;

    out[gid] = r;
}

extern "C" void kernel_launch(void* const* d_in, const int* in_sizes, int n_in,
                              void* d_out, int out_size)
{
    const float*  x     = (const float*)d_in[0];
    const float2* table = (const float2*)d_in[1];
    float2*       out   = (float2*)d_out;

    const int N = in_sizes[0] / 3;

    ResParams rp;
    {
        const double growth = exp((log(128.0) - log(16.0)) / (double)(N_LEVELS - 1));
        for (int l = 0; l < N_LEVELS; ++l) {
            rp.r[l] = (float)floor(16.0 * pow(growth, (double)l));
        }
    }

    const long long total = (long long)N * N_LEVELS;
    const int threads = 256;
    const int blocks = (int)((total + threads - 1) / threads);
    hashgrid_kernel<<<blocks, threads>>>(x, table, out, rp, N);
}